// round 8
// baseline (speedup 1.0000x reference)
#include <cuda_runtime.h>
#include <cuda_bf16.h>
#include <math.h>
#include <stdint.h>

typedef __nv_bfloat16 bf16;

#define B_    16384
#define FIN_  640
#define H1_   1024
#define H2_   512
#define T1_   256
#define T2_   128
#define D_    8

#define DEVFN static __device__ __forceinline__

// ---------------- scratch (static device globals; no allocs allowed) -------
__device__ bf16 g_xb  [B_*FIN_];
__device__ bf16 g_w1t [H1_*FIN_];
__device__ bf16 g_w2t [H2_*H1_];
__device__ bf16 g_tw1t[D_*T1_*H2_];
__device__ bf16 g_tw2t[D_*T2_*T1_];
__device__ bf16 g_h1  [B_*H1_];
__device__ bf16 g_h2  [B_*H2_];
__device__ bf16 g_t1  [B_*T1_];
__device__ int  g_perm[B_];
__device__ int  g_counts[D_];
__device__ int  g_offs[D_];
__device__ int  g_cursor[D_];

// ---------------- helpers ---------------------------------------------------
DEVFN uint32_t smaddr(const void* p){ return (uint32_t)__cvta_generic_to_shared(p); }

DEVFN void cp16(uint32_t s, const void* g){
    asm volatile("cp.async.cg.shared.global [%0], [%1], 16;" :: "r"(s), "l"(g));
}
DEVFN void cp_commit(){ asm volatile("cp.async.commit_group;"); }

DEVFN void ldsm_x4(uint32_t* r, uint32_t addr){
    asm volatile("ldmatrix.sync.aligned.m8n8.x4.shared.b16 {%0,%1,%2,%3}, [%4];"
        : "=r"(r[0]), "=r"(r[1]), "=r"(r[2]), "=r"(r[3]) : "r"(addr));
}

DEVFN void mma16816(float* d, const uint32_t* a, const uint32_t* b){
    asm volatile(
        "mma.sync.aligned.m16n8k16.row.col.f32.bf16.bf16.f32 "
        "{%0,%1,%2,%3}, {%4,%5,%6,%7}, {%8,%9}, {%0,%1,%2,%3};\n"
        : "+f"(d[0]), "+f"(d[1]), "+f"(d[2]), "+f"(d[3])
        : "r"(a[0]), "r"(a[1]), "r"(a[2]), "r"(a[3]), "r"(b[0]), "r"(b[1]));
}

// ---------------- bucket prep: hist + scan in ONE block ---------------------
__global__ __launch_bounds__(1024,1) void bucket_prep_kernel(const int* __restrict__ dom){
    __shared__ int h[D_];
    int tid = threadIdx.x;
    if (tid < D_) h[tid] = 0;
    __syncthreads();
    int c0=0,c1=0,c2=0,c3=0,c4=0,c5=0,c6=0,c7=0;
    #pragma unroll
    for (int k=0;k<16;k++){
        int d = dom[tid + k*1024];
        c0 += (d==0); c1 += (d==1); c2 += (d==2); c3 += (d==3);
        c4 += (d==4); c5 += (d==5); c6 += (d==6); c7 += (d==7);
    }
    #pragma unroll
    for (int off=16; off; off>>=1){
        c0 += __shfl_down_sync(0xffffffffu, c0, off);
        c1 += __shfl_down_sync(0xffffffffu, c1, off);
        c2 += __shfl_down_sync(0xffffffffu, c2, off);
        c3 += __shfl_down_sync(0xffffffffu, c3, off);
        c4 += __shfl_down_sync(0xffffffffu, c4, off);
        c5 += __shfl_down_sync(0xffffffffu, c5, off);
        c6 += __shfl_down_sync(0xffffffffu, c6, off);
        c7 += __shfl_down_sync(0xffffffffu, c7, off);
    }
    if ((tid & 31) == 0){
        atomicAdd(&h[0], c0); atomicAdd(&h[1], c1);
        atomicAdd(&h[2], c2); atomicAdd(&h[3], c3);
        atomicAdd(&h[4], c4); atomicAdd(&h[5], c5);
        atomicAdd(&h[6], c6); atomicAdd(&h[7], c7);
    }
    __syncthreads();
    if (tid == 0){
        int s = 0;
        for (int d=0; d<D_; d++){
            g_offs[d] = s;
            int c = h[d];
            g_counts[d] = c;
            g_cursor[d] = 0;
            s += c;
        }
    }
}

// ---------------- mega prep: scatter + x convert + weight transposes --------
#define PREP_SCATTER  64
#define PREP_CONVX    2560
#define PREP_TILES    2432
#define PREP_BLOCKS   (PREP_SCATTER + PREP_CONVX + PREP_TILES)

DEVFN void trans_tile(const float* __restrict__ src, bf16* __restrict__ dst,
                      int K, int N, int ky, int nx, int tx, int ty,
                      float (*tile)[33]){
    int k0 = ky*32, n0 = nx*32;
    #pragma unroll
    for (int i=0;i<32;i+=8)
        tile[ty+i][tx] = src[(size_t)(k0+ty+i)*N + n0 + tx];
    __syncthreads();
    #pragma unroll
    for (int i=0;i<32;i+=8)
        dst[(size_t)(n0+ty+i)*K + k0 + tx] = __float2bfloat16(tile[tx][ty+i]);
}

__global__ __launch_bounds__(256,1) void prep_kernel(
    const int* __restrict__ dom,
    const float4* __restrict__ x4,
    const float* __restrict__ W1, const float* __restrict__ W2,
    const float* __restrict__ TW1, const float* __restrict__ TW2)
{
    __shared__ float tile[32][33];
    __shared__ int sh[D_], sbase[D_], scur[D_];
    int bid = blockIdx.x, tid = threadIdx.x;

    if (bid < PREP_SCATTER){
        if (tid < D_){ sh[tid]=0; scur[tid]=0; }
        __syncthreads();
        int i = bid*256 + tid;
        int d = dom[i];
        atomicAdd(&sh[d], 1);
        __syncthreads();
        if (tid < D_) sbase[tid] = atomicAdd(&g_cursor[tid], sh[tid]);
        __syncthreads();
        int p = atomicAdd(&scur[d], 1);
        g_perm[g_offs[d] + sbase[d] + p] = i;
        return;
    }
    if (bid < PREP_SCATTER + PREP_CONVX){
        int i0 = (bid - PREP_SCATTER)*1024 + tid;
        #pragma unroll
        for (int k=0;k<4;k++){
            int i = i0 + k*256;
            float4 v = x4[i];
            __nv_bfloat162* o = (__nv_bfloat162*)g_xb + (size_t)i*2;
            o[0] = __floats2bfloat162_rn(v.x, v.y);
            o[1] = __floats2bfloat162_rn(v.z, v.w);
        }
        return;
    }
    int t = bid - (PREP_SCATTER + PREP_CONVX);
    int tx = tid & 31, ty = tid >> 5;
    if (t < 640){
        trans_tile(W1, g_w1t, FIN_, H1_, t/32, t%32, tx, ty, tile);
    } else if (t < 1152){
        int t2 = t - 640;
        trans_tile(W2, g_w2t, H1_, H2_, t2/16, t2%16, tx, ty, tile);
    } else if (t < 2176){
        int t3 = t - 1152;
        int z = t3 >> 7, r = t3 & 127;
        trans_tile(TW1 + (size_t)z*H2_*T1_, g_tw1t + (size_t)z*T1_*H2_,
                   H2_, T1_, r/8, r%8, tx, ty, tile);
    } else {
        int t4 = t - 2176;
        int z = t4 >> 5, r = t4 & 31;
        trans_tile(TW2 + (size_t)z*T1_*T2_, g_tw2t + (size_t)z*T2_*T1_,
                   T1_, T2_, r/4, r%4, tx, ty, tile);
    }
}

// ---------------- HMMA GEMM: 128x64 tile, 32x32 warp tile, 3 CTAs/SM -------
// C[M,N](bf16) = relu(A[M,K] @ Bt[N,K]^T + bias)
// 256 threads, BM=128, BN=64, BK=64, warps 4(M) x 2(N), warp tile 32x32.
template<bool GATHER>
__global__ __launch_bounds__(256,3) void gemm_bf16_kernel(
    const bf16* __restrict__ A,
    const bf16* __restrict__ Bt,
    const float* __restrict__ bias,
    bf16* __restrict__ Cout,
    int M, int N, int K,
    int bt_dstride, int bias_dstride)
{
    constexpr int BM=128, BN=64, BK=64, LDS=BK+8;   // 72 halves/row (144B)
    constexpr int ASTG = BM*LDS;
    constexpr int BSTG = BN*LDS;
    extern __shared__ bf16 sm[];
    bf16* As = sm;                    // 2 stages
    bf16* Bs = sm + 2*ASTG;           // 2 stages
    __shared__ int s_rows[BM];

    int tid = threadIdx.x;
    int m0 = blockIdx.x*BM;
    int n0 = blockIdx.y*BN;

    int cnt = M, rowbase = m0;
    if (GATHER){
        int d = blockIdx.z;
        cnt = g_counts[d];
        if (m0 >= cnt) return;
        rowbase = g_offs[d] + m0;
        for (int r = tid; r < BM; r += 256){
            int p = rowbase + r;
            s_rows[r] = (r < cnt - m0) ? g_perm[p] : g_perm[rowbase];
        }
        Bt   += (size_t)blockIdx.z * bt_dstride;
        bias += (size_t)blockIdx.z * bias_dstride;
        __syncthreads();
    }
    int limit = GATHER ? (cnt - m0) : BM;

    auto load_tile = [&](int st, int kt){
        int k0 = kt*BK;
        #pragma unroll
        for (int i=0;i<4;i++){
            int v = tid + 256*i;
            int r = v>>3, c = v&7;
            int grow = GATHER ? s_rows[r] : (m0 + r);
            cp16(smaddr(&As[st*ASTG + r*LDS + c*8]), A + (size_t)grow*K + k0 + c*8);
        }
        {
            int v = tid;
            int r = v>>3, c = v&7;
            cp16(smaddr(&Bs[st*BSTG + r*LDS + c*8]), Bt + (size_t)(n0 + r)*K + k0 + c*8);
            v = tid + 256;
            r = v>>3; c = v&7;
            cp16(smaddr(&Bs[st*BSTG + r*LDS + c*8]), Bt + (size_t)(n0 + r)*K + k0 + c*8);
        }
    };

    int warp = tid>>5, lane = tid&31;
    int wm = warp & 3, wn = warp >> 2;     // 4 x 2
    int g  = lane>>2,  tg = lane&3;

    // ldmatrix per-lane addressing
    int a_row = wm*32 + (lane&7) + ((lane&8)?8:0);   // + mt*16
    int a_ko  = (lane&16)?8:0;
    int b_row = wn*32 + (lane&7) + ((lane&16)?8:0);  // + ntp*16
    int b_ko  = (lane&8)?8:0;

    float acc[2][4][4];
    #pragma unroll
    for (int a=0;a<2;a++)
        #pragma unroll
        for (int b=0;b<4;b++)
            #pragma unroll
            for (int c=0;c<4;c++) acc[a][b][c]=0.f;

    const int KT = K/BK;
    load_tile(0, 0); cp_commit();
    for (int kt=0; kt<KT; kt++){
        if (kt+1 < KT){
            load_tile((kt+1)&1, kt+1); cp_commit();
            asm volatile("cp.async.wait_group 1;");
        } else {
            asm volatile("cp.async.wait_group 0;");
        }
        __syncthreads();
        uint32_t asb = smaddr(&As[(kt&1)*ASTG]);
        uint32_t bsb = smaddr(&Bs[(kt&1)*BSTG]);
        #pragma unroll
        for (int kk=0; kk<4; kk++){
            uint32_t af[2][4], bf[2][4];
            #pragma unroll
            for (int mt=0; mt<2; mt++)
                ldsm_x4(af[mt], asb + (uint32_t)(((a_row + mt*16)*LDS) + kk*16 + a_ko)*2u);
            #pragma unroll
            for (int ntp=0; ntp<2; ntp++)
                ldsm_x4(bf[ntp], bsb + (uint32_t)(((b_row + ntp*16)*LDS) + kk*16 + b_ko)*2u);
            #pragma unroll
            for (int mt=0; mt<2; mt++)
                #pragma unroll
                for (int ntp=0; ntp<2; ntp++){
                    mma16816(acc[mt][2*ntp],   af[mt], bf[ntp]);
                    mma16816(acc[mt][2*ntp+1], af[mt], bf[ntp]+2);
                }
        }
        __syncthreads();
    }

    // epilogue: bias + relu -> bf16
    #pragma unroll
    for (int nb=0; nb<4; nb++){
        int c = n0 + wn*32 + nb*8 + tg*2;
        float bv0 = bias[c], bv1 = bias[c+1];
        #pragma unroll
        for (int mt=0; mt<2; mt++){
            int rl0 = wm*32 + mt*16 + g;
            int rl1 = rl0 + 8;
            float v00 = fmaxf(acc[mt][nb][0] + bv0, 0.f);
            float v01 = fmaxf(acc[mt][nb][1] + bv1, 0.f);
            float v10 = fmaxf(acc[mt][nb][2] + bv0, 0.f);
            float v11 = fmaxf(acc[mt][nb][3] + bv1, 0.f);
            if (rl0 < limit)
                *(__nv_bfloat162*)&Cout[(size_t)(rowbase+rl0)*N + c] = __floats2bfloat162_rn(v00, v01);
            if (rl1 < limit)
                *(__nv_bfloat162*)&Cout[(size_t)(rowbase+rl1)*N + c] = __floats2bfloat162_rn(v10, v11);
        }
    }
}

// ---------------- fused tower L2 + L3 + sigmoid + scatter ------------------
__global__ __launch_bounds__(128,1) void tower23_kernel(
    const float* __restrict__ Tb2, const float* __restrict__ TWo,
    const float* __restrict__ Tbo, float* __restrict__ out)
{
    constexpr int BM=128, BN=128, BK=32, LDSA=BK+8;
    constexpr int KT = T1_/BK;
    extern __shared__ bf16 smw[];
    bf16* As = smw;
    bf16* Bs = smw + 2*BM*LDSA;
    __shared__ float srow[BM];

    int d = blockIdx.y;
    int cnt = g_counts[d];
    int m0 = blockIdx.x*BM;
    if (m0 >= cnt) return;
    int rbase = g_offs[d] + m0;
    const bf16* Bt = g_tw2t + (size_t)d*T2_*T1_;
    int tid = threadIdx.x;

    auto load_tile = [&](int st, int kt){
        int k0 = kt*BK;
        #pragma unroll
        for (int i=0;i<4;i++){
            int v = tid + 128*i;
            int r = v>>2, c = v&3;
            int arow = rbase + r; if (arow >= B_) arow = B_-1;
            cp16(smaddr(&As[st*BM*LDSA + r*LDSA + c*8]), g_t1 + (size_t)arow*T1_ + k0 + c*8);
            cp16(smaddr(&Bs[st*BN*LDSA + r*LDSA + c*8]), Bt   + (size_t)r   *T1_ + k0 + c*8);
        }
    };

    int warp = tid>>5, lane = tid&31;
    int wm = warp & 1, wn = warp >> 1;
    int g  = lane>>2,  tg = lane&3;

    float acc[4][8][4];
    #pragma unroll
    for (int a=0;a<4;a++)
        #pragma unroll
        for (int b=0;b<8;b++)
            #pragma unroll
            for (int c=0;c<4;c++) acc[a][b][c]=0.f;

    load_tile(0,0); cp_commit();
    for (int kt=0; kt<KT; kt++){
        if (kt+1 < KT){
            load_tile((kt+1)&1, kt+1); cp_commit();
            asm volatile("cp.async.wait_group 1;");
        } else {
            asm volatile("cp.async.wait_group 0;");
        }
        __syncthreads();
        const bf16* as = &As[(kt&1)*BM*LDSA];
        const bf16* bs = &Bs[(kt&1)*BN*LDSA];
        #pragma unroll
        for (int kk=0; kk<2; kk++){
            uint32_t af[4][4], bfr[8][2];
            #pragma unroll
            for (int mt=0; mt<4; mt++){
                int row = wm*64 + mt*16 + g;
                const uint32_t* p  = (const uint32_t*)&as[row*LDSA     + kk*16 + tg*2];
                const uint32_t* p2 = (const uint32_t*)&as[(row+8)*LDSA + kk*16 + tg*2];
                af[mt][0]=p[0]; af[mt][1]=p2[0]; af[mt][2]=p[4]; af[mt][3]=p2[4];
            }
            #pragma unroll
            for (int nt=0; nt<8; nt++){
                int n = wn*64 + nt*8 + g;
                const uint32_t* p = (const uint32_t*)&bs[n*LDSA + kk*16 + tg*2];
                bfr[nt][0]=p[0]; bfr[nt][1]=p[4];
            }
            #pragma unroll
            for (int mt=0; mt<4; mt++)
                #pragma unroll
                for (int nt=0; nt<8; nt++)
                    mma16816(acc[mt][nt], af[mt], bfr[nt]);
        }
        __syncthreads();
    }

    if (tid < BM) srow[tid] = 0.f;
    __syncthreads();

    const float* tb2 = Tb2 + d*T2_;
    const float* wo  = TWo + d*T2_;
    #pragma unroll
    for (int mt=0; mt<4; mt++){
        float s0 = 0.f, s1 = 0.f;
        #pragma unroll
        for (int nt=0; nt<8; nt++){
            int c = wn*64 + nt*8 + tg*2;
            float b0 = tb2[c], b1 = tb2[c+1];
            float w0 = wo[c],  w1 = wo[c+1];
            s0 += fmaxf(acc[mt][nt][0] + b0, 0.f)*w0 + fmaxf(acc[mt][nt][1] + b1, 0.f)*w1;
            s1 += fmaxf(acc[mt][nt][2] + b0, 0.f)*w0 + fmaxf(acc[mt][nt][3] + b1, 0.f)*w1;
        }
        s0 += __shfl_xor_sync(0xffffffffu, s0, 1);
        s0 += __shfl_xor_sync(0xffffffffu, s0, 2);
        s1 += __shfl_xor_sync(0xffffffffu, s1, 1);
        s1 += __shfl_xor_sync(0xffffffffu, s1, 2);
        if (tg == 0){
            int r = wm*64 + mt*16 + g;
            atomicAdd(&srow[r],     s0);
            atomicAdd(&srow[r + 8], s1);
        }
    }
    __syncthreads();

    int r = tid;
    if (r < cnt - m0){
        float logit = srow[r] + Tbo[d];
        out[g_perm[rbase + r]] = 1.f / (1.f + expf(-logit));
    }
}

// ---------------- launch ----------------------------------------------------
extern "C" void kernel_launch(void* const* d_in, const int* in_sizes, int n_in,
                              void* d_out, int out_size)
{
    const float* x    = (const float*)d_in[0];
    const int*   dom  = (const int*)  d_in[1];
    const float* W1   = (const float*)d_in[2];
    const float* b1   = (const float*)d_in[3];
    const float* W2   = (const float*)d_in[4];
    const float* b2   = (const float*)d_in[5];
    const float* TW1  = (const float*)d_in[6];
    const float* Tb1  = (const float*)d_in[7];
    const float* TW2  = (const float*)d_in[8];
    const float* Tb2  = (const float*)d_in[9];
    const float* TWo  = (const float*)d_in[10];
    const float* Tbo  = (const float*)d_in[11];
    float* out = (float*)d_out;

    void *p;
    cudaGetSymbolAddress(&p, g_xb);   bf16* xb   = (bf16*)p;
    cudaGetSymbolAddress(&p, g_w1t);  bf16* w1t  = (bf16*)p;
    cudaGetSymbolAddress(&p, g_w2t);  bf16* w2t  = (bf16*)p;
    cudaGetSymbolAddress(&p, g_tw1t); bf16* tw1t = (bf16*)p;
    cudaGetSymbolAddress(&p, g_h1);   bf16* h1   = (bf16*)p;
    cudaGetSymbolAddress(&p, g_h2);   bf16* h2   = (bf16*)p;
    cudaGetSymbolAddress(&p, g_t1);   bf16* t1   = (bf16*)p;

    // smem: 2 stages * (128 + 64) * 72 halves * 2B = 55296
    const int GEMM_SMEM = 2*(128+64)*72*(int)sizeof(bf16);
    cudaFuncSetAttribute(gemm_bf16_kernel<false>, cudaFuncAttributeMaxDynamicSharedMemorySize, GEMM_SMEM);
    cudaFuncSetAttribute(gemm_bf16_kernel<true>,  cudaFuncAttributeMaxDynamicSharedMemorySize, GEMM_SMEM);
    const int T23_SMEM = (2*128*40 + 2*128*40) * (int)sizeof(bf16);

    // 1) bucket hist+scan (single block)
    bucket_prep_kernel<<<1, 1024>>>(dom);

    // 2) mega prep: scatter + x convert + all weight transposes
    prep_kernel<<<PREP_BLOCKS, 256>>>(dom, (const float4*)x, W1, W2, TW1, TW2);

    // 3) bottom MLP
    gemm_bf16_kernel<false><<<dim3(B_/128, H1_/64, 1), 256, GEMM_SMEM>>>(
        xb, w1t, b1, h1, B_, H1_, FIN_, 0, 0);
    gemm_bf16_kernel<false><<<dim3(B_/128, H2_/64, 1), 256, GEMM_SMEM>>>(
        h1, w2t, b2, h2, B_, H2_, H1_, 0, 0);

    // 4) tower layer 1 (grouped, gathered)
    gemm_bf16_kernel<true><<<dim3(B_/128, T1_/64, D_), 256, GEMM_SMEM>>>(
        h2, tw1t, Tb1, t1, B_, T1_, H2_, T1_*H2_, T1_);

    // 5) tower layers 2+3 fused + sigmoid + scatter
    tower23_kernel<<<dim3(B_/128, D_, 1), 128, T23_SMEM>>>(Tb2, TWo, Tbo, out);
}

// round 9
// speedup vs baseline: 1.0919x; 1.0919x over previous
#include <cuda_runtime.h>
#include <cuda_bf16.h>
#include <math.h>
#include <stdint.h>

typedef __nv_bfloat16 bf16;

#define B_    16384
#define FIN_  640
#define H1_   1024
#define H2_   512
#define T1_   256
#define T2_   128
#define D_    8

#define DEVFN static __device__ __forceinline__

// ---------------- scratch (static device globals; no allocs allowed) -------
__device__ bf16 g_xb  [B_*FIN_];
__device__ bf16 g_w1t [H1_*FIN_];
__device__ bf16 g_w2t [H2_*H1_];
__device__ bf16 g_tw1t[D_*T1_*H2_];
__device__ bf16 g_tw2t[D_*T2_*T1_];
__device__ bf16 g_h1  [B_*H1_];
__device__ bf16 g_h2  [B_*H2_];
__device__ int  g_perm[B_];
__device__ int  g_counts[D_];
__device__ int  g_offs[D_];
__device__ int  g_cursor[D_];

// ---------------- helpers ---------------------------------------------------
DEVFN uint32_t smaddr(const void* p){ return (uint32_t)__cvta_generic_to_shared(p); }

DEVFN void cp16(uint32_t s, const void* g){
    asm volatile("cp.async.cg.shared.global [%0], [%1], 16;" :: "r"(s), "l"(g));
}
DEVFN void cp_commit(){ asm volatile("cp.async.commit_group;"); }

DEVFN void ldsm_x4(uint32_t* r, uint32_t addr){
    asm volatile("ldmatrix.sync.aligned.m8n8.x4.shared.b16 {%0,%1,%2,%3}, [%4];"
        : "=r"(r[0]), "=r"(r[1]), "=r"(r[2]), "=r"(r[3]) : "r"(addr));
}

DEVFN void mma16816(float* d, const uint32_t* a, const uint32_t* b){
    asm volatile(
        "mma.sync.aligned.m16n8k16.row.col.f32.bf16.bf16.f32 "
        "{%0,%1,%2,%3}, {%4,%5,%6,%7}, {%8,%9}, {%0,%1,%2,%3};\n"
        : "+f"(d[0]), "+f"(d[1]), "+f"(d[2]), "+f"(d[3])
        : "r"(a[0]), "r"(a[1]), "r"(a[2]), "r"(a[3]), "r"(b[0]), "r"(b[1]));
}

// ---------------- bucket prep: hist + scan in ONE block ---------------------
__global__ __launch_bounds__(1024,1) void bucket_prep_kernel(const int* __restrict__ dom){
    __shared__ int h[D_];
    int tid = threadIdx.x;
    if (tid < D_) h[tid] = 0;
    __syncthreads();
    int c0=0,c1=0,c2=0,c3=0,c4=0,c5=0,c6=0,c7=0;
    #pragma unroll
    for (int k=0;k<16;k++){
        int d = dom[tid + k*1024];
        c0 += (d==0); c1 += (d==1); c2 += (d==2); c3 += (d==3);
        c4 += (d==4); c5 += (d==5); c6 += (d==6); c7 += (d==7);
    }
    #pragma unroll
    for (int off=16; off; off>>=1){
        c0 += __shfl_down_sync(0xffffffffu, c0, off);
        c1 += __shfl_down_sync(0xffffffffu, c1, off);
        c2 += __shfl_down_sync(0xffffffffu, c2, off);
        c3 += __shfl_down_sync(0xffffffffu, c3, off);
        c4 += __shfl_down_sync(0xffffffffu, c4, off);
        c5 += __shfl_down_sync(0xffffffffu, c5, off);
        c6 += __shfl_down_sync(0xffffffffu, c6, off);
        c7 += __shfl_down_sync(0xffffffffu, c7, off);
    }
    if ((tid & 31) == 0){
        atomicAdd(&h[0], c0); atomicAdd(&h[1], c1);
        atomicAdd(&h[2], c2); atomicAdd(&h[3], c3);
        atomicAdd(&h[4], c4); atomicAdd(&h[5], c5);
        atomicAdd(&h[6], c6); atomicAdd(&h[7], c7);
    }
    __syncthreads();
    if (tid == 0){
        int s = 0;
        for (int d=0; d<D_; d++){
            g_offs[d] = s;
            int c = h[d];
            g_counts[d] = c;
            g_cursor[d] = 0;
            s += c;
        }
    }
}

// ---------------- mega prep: scatter + x convert + weight transposes --------
#define PREP_SCATTER  64
#define PREP_CONVX    2560
#define PREP_TILES    2432
#define PREP_BLOCKS   (PREP_SCATTER + PREP_CONVX + PREP_TILES)

DEVFN void trans_tile(const float* __restrict__ src, bf16* __restrict__ dst,
                      int K, int N, int ky, int nx, int tx, int ty,
                      float (*tile)[33]){
    int k0 = ky*32, n0 = nx*32;
    #pragma unroll
    for (int i=0;i<32;i+=8)
        tile[ty+i][tx] = src[(size_t)(k0+ty+i)*N + n0 + tx];
    __syncthreads();
    #pragma unroll
    for (int i=0;i<32;i+=8)
        dst[(size_t)(n0+ty+i)*K + k0 + tx] = __float2bfloat16(tile[tx][ty+i]);
}

__global__ __launch_bounds__(256,1) void prep_kernel(
    const int* __restrict__ dom,
    const float4* __restrict__ x4,
    const float* __restrict__ W1, const float* __restrict__ W2,
    const float* __restrict__ TW1, const float* __restrict__ TW2)
{
    __shared__ float tile[32][33];
    __shared__ int sh[D_], sbase[D_], scur[D_];
    int bid = blockIdx.x, tid = threadIdx.x;

    if (bid < PREP_SCATTER){
        if (tid < D_){ sh[tid]=0; scur[tid]=0; }
        __syncthreads();
        int i = bid*256 + tid;
        int d = dom[i];
        atomicAdd(&sh[d], 1);
        __syncthreads();
        if (tid < D_) sbase[tid] = atomicAdd(&g_cursor[tid], sh[tid]);
        __syncthreads();
        int p = atomicAdd(&scur[d], 1);
        g_perm[g_offs[d] + sbase[d] + p] = i;
        return;
    }
    if (bid < PREP_SCATTER + PREP_CONVX){
        int i0 = (bid - PREP_SCATTER)*1024 + tid;
        #pragma unroll
        for (int k=0;k<4;k++){
            int i = i0 + k*256;
            float4 v = x4[i];
            __nv_bfloat162* o = (__nv_bfloat162*)g_xb + (size_t)i*2;
            o[0] = __floats2bfloat162_rn(v.x, v.y);
            o[1] = __floats2bfloat162_rn(v.z, v.w);
        }
        return;
    }
    int t = bid - (PREP_SCATTER + PREP_CONVX);
    int tx = tid & 31, ty = tid >> 5;
    if (t < 640){
        trans_tile(W1, g_w1t, FIN_, H1_, t/32, t%32, tx, ty, tile);
    } else if (t < 1152){
        int t2 = t - 640;
        trans_tile(W2, g_w2t, H1_, H2_, t2/16, t2%16, tx, ty, tile);
    } else if (t < 2176){
        int t3 = t - 1152;
        int z = t3 >> 7, r = t3 & 127;
        trans_tile(TW1 + (size_t)z*H2_*T1_, g_tw1t + (size_t)z*T1_*H2_,
                   H2_, T1_, r/8, r%8, tx, ty, tile);
    } else {
        int t4 = t - 2176;
        int z = t4 >> 5, r = t4 & 31;
        trans_tile(TW2 + (size_t)z*T1_*T2_, g_tw2t + (size_t)z*T2_*T1_,
                   T1_, T2_, r/4, r%4, tx, ty, tile);
    }
}

// ---------------- HMMA GEMM (R5 proven config): 128x128, 2 CTAs/SM ---------
// C[M,N](bf16) = relu(A[M,K] @ Bt[N,K]^T + bias)
__global__ __launch_bounds__(256,2) void gemm_bf16_kernel(
    const bf16* __restrict__ A,
    const bf16* __restrict__ Bt,
    const float* __restrict__ bias,
    bf16* __restrict__ Cout,
    int M, int N, int K)
{
    constexpr int BM=128, BN=128, BK=64, LDS=BK+8;
    constexpr int STG = BM*LDS;
    extern __shared__ bf16 sm[];
    bf16* As = sm;
    bf16* Bs = sm + 2*STG;

    int tid = threadIdx.x;
    int m0 = blockIdx.x*BM;
    int n0 = blockIdx.y*BN;

    auto load_tile = [&](int st, int kt){
        int k0 = kt*BK;
        #pragma unroll
        for (int i=0;i<4;i++){
            int v = tid + 256*i;
            int r = v>>3, c = v&7;
            cp16(smaddr(&As[st*STG + r*LDS + c*8]), A + (size_t)(m0 + r)*K + k0 + c*8);
        }
        #pragma unroll
        for (int i=0;i<4;i++){
            int v = tid + 256*i;
            int r = v>>3, c = v&7;
            cp16(smaddr(&Bs[st*STG + r*LDS + c*8]), Bt + (size_t)(n0 + r)*K + k0 + c*8);
        }
    };

    int warp = tid>>5, lane = tid&31;
    int wm = warp & 3, wn = warp >> 2;     // 4 x 2
    int g  = lane>>2,  tg = lane&3;

    int a_row = wm*32 + (lane&7) + ((lane&8)?8:0);
    int a_ko  = (lane&16)?8:0;
    int b_row = wn*64 + (lane&7) + ((lane&16)?8:0);
    int b_ko  = (lane&8)?8:0;

    float acc[2][8][4];
    #pragma unroll
    for (int a=0;a<2;a++)
        #pragma unroll
        for (int b=0;b<8;b++)
            #pragma unroll
            for (int c=0;c<4;c++) acc[a][b][c]=0.f;

    const int KT = K/BK;
    load_tile(0, 0); cp_commit();
    for (int kt=0; kt<KT; kt++){
        if (kt+1 < KT){
            load_tile((kt+1)&1, kt+1); cp_commit();
            asm volatile("cp.async.wait_group 1;");
        } else {
            asm volatile("cp.async.wait_group 0;");
        }
        __syncthreads();
        uint32_t asb = smaddr(&As[(kt&1)*STG]);
        uint32_t bsb = smaddr(&Bs[(kt&1)*STG]);
        #pragma unroll
        for (int kk=0; kk<4; kk++){
            uint32_t af[2][4];
            #pragma unroll
            for (int mt=0; mt<2; mt++)
                ldsm_x4(af[mt], asb + (uint32_t)(((a_row + mt*16)*LDS) + kk*16 + a_ko)*2u);
            #pragma unroll
            for (int ntp=0; ntp<4; ntp++){
                uint32_t bf[4];
                ldsm_x4(bf, bsb + (uint32_t)(((b_row + ntp*16)*LDS) + kk*16 + b_ko)*2u);
                #pragma unroll
                for (int mt=0; mt<2; mt++){
                    mma16816(acc[mt][2*ntp],   af[mt], bf);
                    mma16816(acc[mt][2*ntp+1], af[mt], bf+2);
                }
            }
        }
        __syncthreads();
    }

    #pragma unroll
    for (int nt=0; nt<8; nt++){
        int c = n0 + wn*64 + nt*8 + tg*2;
        float bv0 = bias[c], bv1 = bias[c+1];
        #pragma unroll
        for (int mt=0; mt<2; mt++){
            int rl0 = wm*32 + mt*16 + g;
            int rl1 = rl0 + 8;
            float v00 = fmaxf(acc[mt][nt][0] + bv0, 0.f);
            float v01 = fmaxf(acc[mt][nt][1] + bv1, 0.f);
            float v10 = fmaxf(acc[mt][nt][2] + bv0, 0.f);
            float v11 = fmaxf(acc[mt][nt][3] + bv1, 0.f);
            *(__nv_bfloat162*)&Cout[(size_t)(m0+rl0)*N + c] = __floats2bfloat162_rn(v00, v01);
            *(__nv_bfloat162*)&Cout[(size_t)(m0+rl1)*N + c] = __floats2bfloat162_rn(v10, v11);
        }
    }
}

// ---------------- FUSED tower: L1 + L2 + L3 + sigmoid + scatter -------------
// Per (m-block, domain) CTA:
//   phase1: t1 = relu(h2[perm rows] @ TW1[d]^T + Tb1[d])  -> smem (two N-halves)
//   phase2: t2 = relu(t1 @ TW2[d]^T + Tb2[d]); logit = t2.TWo[d]+Tbo[d]; out.
// 256 threads, warps 4(M)x2(N).
#define TW_PIPE_BYTES  (4*128*72*2)          /* 73728: 2-stage A+B pipeline  */
#define TW_T1_LDS      264                   /* padded halves per t1 row     */
#define TW_T1_BYTES    (128*TW_T1_LDS*2)     /* 67584                        */
#define TW_SMEM        (TW_PIPE_BYTES + TW_T1_BYTES)

__global__ __launch_bounds__(256,1) void tower_kernel(
    const float* __restrict__ Tb1,   // [D][256]
    const float* __restrict__ Tb2,   // [D][128]
    const float* __restrict__ TWo,   // [D][128]
    const float* __restrict__ Tbo,   // [D][1]
    float* __restrict__ out)
{
    constexpr int BM=128, BK=64, LDS=BK+8;    // phase1 pipeline rows
    constexpr int STG = BM*LDS;               // halves per operand stage
    extern __shared__ bf16 sm[];
    bf16* As  = sm;                           // pipeline A (2 stages)
    bf16* Bs  = sm + 2*STG;                   // pipeline B (2 stages)
    bf16* t1s = sm + (TW_PIPE_BYTES/2);       // t1 region [128][264]
    __shared__ int s_rows[BM];
    __shared__ float srow[BM];

    int tid = threadIdx.x;
    int d = blockIdx.y;
    int cnt = g_counts[d];
    int m0 = blockIdx.x*BM;
    if (m0 >= cnt) return;
    int rbase = g_offs[d] + m0;
    int limit = min(BM, cnt - m0);
    for (int r = tid; r < BM; r += 256)
        s_rows[r] = (r < limit) ? g_perm[rbase + r] : g_perm[rbase];
    if (tid < BM) srow[tid] = 0.f;
    __syncthreads();

    const bf16* Bt1 = g_tw1t + (size_t)d*T1_*H2_;   // [256][512]
    const bf16* Bt2 = g_tw2t + (size_t)d*T2_*T1_;   // [128][256]
    const float* tb1 = Tb1 + d*T1_;
    const float* tb2 = Tb2 + d*T2_;
    const float* wo  = TWo + d*T2_;

    int warp = tid>>5, lane = tid&31;
    int wm = warp & 3, wn = warp >> 2;     // 4 x 2
    int g  = lane>>2,  tg = lane&3;

    int a_row = wm*32 + (lane&7) + ((lane&8)?8:0);
    int a_ko  = (lane&16)?8:0;
    int b_row = wn*64 + (lane&7) + ((lane&16)?8:0);
    int b_ko  = (lane&8)?8:0;

    float acc[2][8][4];

    // ================= phase 1: two N-halves of T1 =================
    auto load1 = [&](int st, int kt, int nh){
        int k0 = kt*BK;
        #pragma unroll
        for (int i=0;i<4;i++){
            int v = tid + 256*i;
            int r = v>>3, c = v&7;
            cp16(smaddr(&As[st*STG + r*LDS + c*8]), g_h2 + (size_t)s_rows[r]*H2_ + k0 + c*8);
        }
        #pragma unroll
        for (int i=0;i<4;i++){
            int v = tid + 256*i;
            int r = v>>3, c = v&7;
            cp16(smaddr(&Bs[st*STG + r*LDS + c*8]), Bt1 + (size_t)(nh*128 + r)*H2_ + k0 + c*8);
        }
    };

    #pragma unroll
    for (int nh=0; nh<2; nh++){
        #pragma unroll
        for (int a=0;a<2;a++)
            #pragma unroll
            for (int b=0;b<8;b++)
                #pragma unroll
                for (int c=0;c<4;c++) acc[a][b][c]=0.f;

        constexpr int KT = H2_/BK;   // 8
        load1(0, 0, nh); cp_commit();
        for (int kt=0; kt<KT; kt++){
            if (kt+1 < KT){
                load1((kt+1)&1, kt+1, nh); cp_commit();
                asm volatile("cp.async.wait_group 1;");
            } else {
                asm volatile("cp.async.wait_group 0;");
            }
            __syncthreads();
            uint32_t asb = smaddr(&As[(kt&1)*STG]);
            uint32_t bsb = smaddr(&Bs[(kt&1)*STG]);
            #pragma unroll
            for (int kk=0; kk<4; kk++){
                uint32_t af[2][4];
                #pragma unroll
                for (int mt=0; mt<2; mt++)
                    ldsm_x4(af[mt], asb + (uint32_t)(((a_row + mt*16)*LDS) + kk*16 + a_ko)*2u);
                #pragma unroll
                for (int ntp=0; ntp<4; ntp++){
                    uint32_t bf[4];
                    ldsm_x4(bf, bsb + (uint32_t)(((b_row + ntp*16)*LDS) + kk*16 + b_ko)*2u);
                    #pragma unroll
                    for (int mt=0; mt<2; mt++){
                        mma16816(acc[mt][2*ntp],   af[mt], bf);
                        mma16816(acc[mt][2*ntp+1], af[mt], bf+2);
                    }
                }
            }
            __syncthreads();
        }

        // write t1 half -> smem (bias + relu)
        #pragma unroll
        for (int nt=0; nt<8; nt++){
            int c = nh*128 + wn*64 + nt*8 + tg*2;
            float bv0 = tb1[c], bv1 = tb1[c+1];
            #pragma unroll
            for (int mt=0; mt<2; mt++){
                int rl0 = wm*32 + mt*16 + g;
                int rl1 = rl0 + 8;
                float v00 = fmaxf(acc[mt][nt][0] + bv0, 0.f);
                float v01 = fmaxf(acc[mt][nt][1] + bv1, 0.f);
                float v10 = fmaxf(acc[mt][nt][2] + bv0, 0.f);
                float v11 = fmaxf(acc[mt][nt][3] + bv1, 0.f);
                *(__nv_bfloat162*)&t1s[rl0*TW_T1_LDS + c] = __floats2bfloat162_rn(v00, v01);
                *(__nv_bfloat162*)&t1s[rl1*TW_T1_LDS + c] = __floats2bfloat162_rn(v10, v11);
            }
        }
    }
    __syncthreads();

    // ================= load TW2[d] into pipeline region ==============
    // [128][264] padded rows; 128 rows x 32 chunks of 16B
    {
        uint32_t dstb = smaddr(As);
        #pragma unroll
        for (int i=0;i<16;i++){
            int v = tid + 256*i;
            int r = v>>5, c = v&31;
            cp16(dstb + (uint32_t)(r*(TW_T1_LDS*2) + c*16), Bt2 + (size_t)r*T1_ + c*8);
        }
        cp_commit();
        asm volatile("cp.async.wait_group 0;");
        __syncthreads();
    }

    // ================= phase 2: t2 = relu(t1 @ TW2^T + Tb2) ==========
    #pragma unroll
    for (int a=0;a<2;a++)
        #pragma unroll
        for (int b=0;b<8;b++)
            #pragma unroll
            for (int c=0;c<4;c++) acc[a][b][c]=0.f;

    {
        uint32_t t1b = smaddr(t1s);
        uint32_t twb = smaddr(As);
        #pragma unroll
        for (int kk=0; kk<16; kk++){   // K = 256 = 16 x k16
            uint32_t af[2][4];
            #pragma unroll
            for (int mt=0; mt<2; mt++)
                ldsm_x4(af[mt], t1b + (uint32_t)(((a_row + mt*16)*TW_T1_LDS) + kk*16 + a_ko)*2u);
            #pragma unroll
            for (int ntp=0; ntp<4; ntp++){
                uint32_t bf[4];
                ldsm_x4(bf, twb + (uint32_t)(((b_row + ntp*16)*TW_T1_LDS) + kk*16 + b_ko)*2u);
                #pragma unroll
                for (int mt=0; mt<2; mt++){
                    mma16816(acc[mt][2*ntp],   af[mt], bf);
                    mma16816(acc[mt][2*ntp+1], af[mt], bf+2);
                }
            }
        }
    }

    // ================= logit + sigmoid + scatter =====================
    #pragma unroll
    for (int mt=0; mt<2; mt++){
        float s0 = 0.f, s1 = 0.f;
        #pragma unroll
        for (int nt=0; nt<8; nt++){
            int c = wn*64 + nt*8 + tg*2;
            float b0 = tb2[c], b1 = tb2[c+1];
            float w0 = wo[c],  w1 = wo[c+1];
            s0 += fmaxf(acc[mt][nt][0] + b0, 0.f)*w0 + fmaxf(acc[mt][nt][1] + b1, 0.f)*w1;
            s1 += fmaxf(acc[mt][nt][2] + b0, 0.f)*w0 + fmaxf(acc[mt][nt][3] + b1, 0.f)*w1;
        }
        s0 += __shfl_xor_sync(0xffffffffu, s0, 1);
        s0 += __shfl_xor_sync(0xffffffffu, s0, 2);
        s1 += __shfl_xor_sync(0xffffffffu, s1, 1);
        s1 += __shfl_xor_sync(0xffffffffu, s1, 2);
        if (tg == 0){
            int r = wm*32 + mt*16 + g;
            atomicAdd(&srow[r],     s0);
            atomicAdd(&srow[r + 8], s1);
        }
    }
    __syncthreads();

    if (tid < BM && tid < limit){
        float logit = srow[tid] + Tbo[d];
        out[g_perm[rbase + tid]] = 1.f / (1.f + expf(-logit));
    }
}

// ---------------- launch ----------------------------------------------------
extern "C" void kernel_launch(void* const* d_in, const int* in_sizes, int n_in,
                              void* d_out, int out_size)
{
    const float* x    = (const float*)d_in[0];
    const int*   dom  = (const int*)  d_in[1];
    const float* W1   = (const float*)d_in[2];
    const float* b1   = (const float*)d_in[3];
    const float* W2   = (const float*)d_in[4];
    const float* b2   = (const float*)d_in[5];
    const float* TW1  = (const float*)d_in[6];
    const float* Tb1  = (const float*)d_in[7];
    const float* TW2  = (const float*)d_in[8];
    const float* Tb2  = (const float*)d_in[9];
    const float* TWo  = (const float*)d_in[10];
    const float* Tbo  = (const float*)d_in[11];
    float* out = (float*)d_out;

    void *p;
    cudaGetSymbolAddress(&p, g_xb);   bf16* xb   = (bf16*)p;
    cudaGetSymbolAddress(&p, g_w1t);  bf16* w1t  = (bf16*)p;
    cudaGetSymbolAddress(&p, g_w2t);  bf16* w2t  = (bf16*)p;
    cudaGetSymbolAddress(&p, g_h1);   bf16* h1   = (bf16*)p;
    cudaGetSymbolAddress(&p, g_h2);   bf16* h2   = (bf16*)p;

    const int GEMM_SMEM = (2*128*72 + 2*128*72) * (int)sizeof(bf16);  // 73728
    cudaFuncSetAttribute(gemm_bf16_kernel, cudaFuncAttributeMaxDynamicSharedMemorySize, GEMM_SMEM);
    cudaFuncSetAttribute(tower_kernel,     cudaFuncAttributeMaxDynamicSharedMemorySize, TW_SMEM);

    // 1) bucket hist+scan (single block)
    bucket_prep_kernel<<<1, 1024>>>(dom);

    // 2) mega prep: scatter + x convert + all weight transposes
    prep_kernel<<<PREP_BLOCKS, 256>>>(dom, (const float4*)x, W1, W2, TW1, TW2);

    // 3) bottom MLP
    gemm_bf16_kernel<<<dim3(B_/128, H1_/128), 256, GEMM_SMEM>>>(
        xb, w1t, b1, h1, B_, H1_, FIN_);
    gemm_bf16_kernel<<<dim3(B_/128, H2_/128), 256, GEMM_SMEM>>>(
        h1, w2t, b2, h2, B_, H2_, H1_);

    // 4) fused towers: L1+L2+L3 + sigmoid + scatter
    tower_kernel<<<dim3(B_/128, D_), 256, TW_SMEM>>>(Tb1, Tb2, TWo, Tbo, out);
}